// round 1
// baseline (speedup 1.0000x reference)
#include <cuda_runtime.h>
#include <cstdint>

// Problem constants
#define NVEH 16384
#define NT   256
#define HDIM 20

// 4 lanes per vehicle, 5 units per lane, 64 threads/block -> 16 vehicles/block
#define TPB  64
#define VPB  16
#define NBLK (NVEH / VPB)   // 1024

// ---------- packed f32x2 helpers (sm_103a) ----------
__device__ __forceinline__ void ffma2(unsigned long long& d,
                                      unsigned long long a,
                                      unsigned long long b) {
    asm("fma.rn.f32x2 %0, %1, %2, %0;" : "+l"(d) : "l"(a), "l"(b));
}
__device__ __forceinline__ unsigned long long dup2(float x) {
    unsigned long long r;
    asm("mov.b64 %0, {%1, %1};" : "=l"(r) : "f"(x));
    return r;
}
__device__ __forceinline__ float lo32(unsigned long long v) {
    float f;
    asm("{ .reg .b32 hi; mov.b64 {%0, hi}, %1; }" : "=f"(f) : "l"(v));
    return f;
}
__device__ __forceinline__ float hi32(unsigned long long v) {
    float f;
    asm("{ .reg .b32 lo; mov.b64 {lo, %0}, %1; }" : "=f"(f) : "l"(v));
    return f;
}

// ---------- fast, overflow-safe activations ----------
// tanh(x) = sign(x) * (1 - e) / (1 + e),  e = exp(-2|x|)  (e <= 1, no overflow)
__device__ __forceinline__ float fast_tanh(float x) {
    float a = fabsf(x);
    float e = __expf(-2.0f * a);
    float r = __fdividef(1.0f - e, 1.0f + e);
    return copysignf(r, x);
}
// sigmoid(x) = 0.5 * (1 + tanh(x/2)); tanh(x/2) uses e = exp(-|x|)
__device__ __forceinline__ float fast_sig(float x) {
    float a = fabsf(x);
    float e = __expf(-a);
    float r = __fdividef(1.0f - e, 1.0f + e);
    return fmaf(0.5f, copysignf(r, x), 0.5f);
}

__global__ __launch_bounds__(TPB, 8)
void rnncf_kernel(const float* __restrict__ lead_inputs,  // (NVEH, NT, 2)
                  const float* __restrict__ init_state,   // (NVEH, 2)
                  const float* __restrict__ h0,           // (NVEH, H)
                  const float* __restrict__ c0,           // (NVEH, H)
                  const float* __restrict__ W,            // (3, 80)
                  const float* __restrict__ U,            // (20, 80)
                  const float* __restrict__ b,            // (80,)
                  const float* __restrict__ Wd,           // (20, 1)
                  const float* __restrict__ bd,           // (1,)
                  float* __restrict__ out,
                  int out_size)
{
    // Shared packed weights: entry [k][j] = {W[k][j], W[k][20+j], W[k][40+j], W[k][60+j]}
    // stored as double2 (.x = (i,f) pair bits, .y = (g,o) pair bits)
    __shared__ double2 Up2[HDIM * HDIM];   // 400 * 16B = 6400B
    __shared__ double2 Wp2[3 * HDIM];      // 60  * 16B
    __shared__ double2 bp2[HDIM];          // 20  * 16B

    {
        float* Upf = reinterpret_cast<float*>(Up2);
        float* Wpf = reinterpret_cast<float*>(Wp2);
        float* bpf = reinterpret_cast<float*>(bp2);
        for (int idx = threadIdx.x; idx < HDIM * 80; idx += TPB) {
            int k = idx / 80, rem = idx % 80;
            int j = rem >> 2, g = rem & 3;
            Upf[idx] = U[k * 80 + g * HDIM + j];
        }
        for (int idx = threadIdx.x; idx < 3 * 80; idx += TPB) {
            int k = idx / 80, rem = idx % 80;
            int j = rem >> 2, g = rem & 3;
            Wpf[idx] = W[k * 80 + g * HDIM + j];
        }
        for (int idx = threadIdx.x; idx < 80; idx += TPB) {
            int j = idx >> 2, g = idx & 3;
            bpf[idx] = b[g * HDIM + j];
        }
    }
    __syncthreads();

    const int lane  = threadIdx.x & 31;
    const int qlane = lane & 3;            // gate-quad lane: owns units [5*qlane, 5*qlane+5)
    const int qbase = lane & ~3;
    const int v     = blockIdx.x * VPB + (threadIdx.x >> 2);
    const int j0    = qlane * 5;

    // Per-lane state
    float hloc[5], cc[5], wdr[5];
#pragma unroll
    for (int u = 0; u < 5; ++u) {
        hloc[u] = h0[v * HDIM + j0 + u];
        cc[u]   = c0[v * HDIM + j0 + u];
        wdr[u]  = Wd[j0 + u];
    }
    const float bdv = bd[0];
    float pos = init_state[2 * v];
    float spd = init_state[2 * v + 1];

    const float2* lead2 = reinterpret_cast<const float2*>(lead_inputs) + (size_t)v * NT;
    float2 cur = lead2[0];

    const bool write_extras = (out_size >= NT * NVEH + NVEH + 2 * NVEH * HDIM);

#pragma unroll 1
    for (int t = 0; t < NT; ++t) {
        // prefetch next step's lead data
        const int tn = (t + 1 < NT) ? (t + 1) : (NT - 1);
        float2 nxt = lead2[tn];

        const float curhd = (cur.x - pos) * (1.0f / 100.0f);
        const float nv    = spd * (1.0f / 40.0f);
        const float lv    = cur.y * (1.0f / 40.0f);

        unsigned long long acc_if[5], acc_go[5];
#pragma unroll
        for (int u = 0; u < 5; ++u) {
            double2 bb = bp2[j0 + u];
            acc_if[u] = __double_as_longlong(bb.x);
            acc_go[u] = __double_as_longlong(bb.y);
        }

        // x @ W  (3 features)
        {
            const float xs0 = curhd, xs1 = nv, xs2 = lv;
            unsigned long long xd;
            xd = dup2(xs0);
#pragma unroll
            for (int u = 0; u < 5; ++u) {
                double2 w = Wp2[0 * HDIM + j0 + u];
                ffma2(acc_if[u], __double_as_longlong(w.x), xd);
                ffma2(acc_go[u], __double_as_longlong(w.y), xd);
            }
            xd = dup2(xs1);
#pragma unroll
            for (int u = 0; u < 5; ++u) {
                double2 w = Wp2[1 * HDIM + j0 + u];
                ffma2(acc_if[u], __double_as_longlong(w.x), xd);
                ffma2(acc_go[u], __double_as_longlong(w.y), xd);
            }
            xd = dup2(xs2);
#pragma unroll
            for (int u = 0; u < 5; ++u) {
                double2 w = Wp2[2 * HDIM + j0 + u];
                ffma2(acc_if[u], __double_as_longlong(w.x), xd);
                ffma2(acc_go[u], __double_as_longlong(w.y), xd);
            }
        }

        // h @ U  (20 hidden) — broadcast h across the quad via shuffles
#pragma unroll
        for (int k = 0; k < HDIM; ++k) {
            float hk = __shfl_sync(0xffffffffu, hloc[k % 5], qbase + (k / 5));
            unsigned long long hd = dup2(hk);
#pragma unroll
            for (int u = 0; u < 5; ++u) {
                double2 uu = Up2[k * HDIM + j0 + u];
                ffma2(acc_if[u], __double_as_longlong(uu.x), hd);
                ffma2(acc_go[u], __double_as_longlong(uu.y), hd);
            }
        }

        // gates -> c, h update for owned units; partial h@Wd
        float p = 0.0f;
#pragma unroll
        for (int u = 0; u < 5; ++u) {
            float zi = lo32(acc_if[u]);
            float zf = hi32(acc_if[u]);
            float zg = lo32(acc_go[u]);
            float zo = hi32(acc_go[u]);
            float ig = fast_sig(zi);
            float fg = fast_sig(zf);
            float gg = fast_tanh(zg);
            float og = fast_sig(zo);
            float cn = fmaf(fg, cc[u], ig * gg);
            cc[u] = cn;
            float hn = og * fast_tanh(cn);
            hloc[u] = hn;
            p = fmaf(hn, wdr[u], p);
        }
        // quad reduction of Wd dot
        p += __shfl_xor_sync(0xffffffffu, p, 1);
        p += __shfl_xor_sync(0xffffffffu, p, 2);

        const float o_scalar = p + bdv;
        const float a = fmaf(7.0f, o_scalar, -4.0f);   // (MAXA-MINA)*out + MINA
        spd = fmaf(0.1f, a, spd);
        pos = fmaf(0.1f, a, pos);

        if (qlane == 0)
            out[(size_t)t * NVEH + v] = pos;

        cur = nxt;
    }

    if (write_extras) {
        if (qlane == 0)
            out[(size_t)NT * NVEH + v] = spd;
        float* hout = out + (size_t)NT * NVEH + NVEH;
        float* cout = hout + (size_t)NVEH * HDIM;
#pragma unroll
        for (int u = 0; u < 5; ++u) {
            hout[v * HDIM + j0 + u] = hloc[u];
            cout[v * HDIM + j0 + u] = cc[u];
        }
    }
}

extern "C" void kernel_launch(void* const* d_in, const int* in_sizes, int n_in,
                              void* d_out, int out_size) {
    const float* lead_inputs = (const float*)d_in[0];
    const float* init_state  = (const float*)d_in[1];
    const float* h0          = (const float*)d_in[2];
    const float* c0          = (const float*)d_in[3];
    const float* W           = (const float*)d_in[4];
    const float* U           = (const float*)d_in[5];
    const float* b           = (const float*)d_in[6];
    const float* Wd          = (const float*)d_in[7];
    const float* bd          = (const float*)d_in[8];

    rnncf_kernel<<<NBLK, TPB>>>(lead_inputs, init_state, h0, c0,
                                W, U, b, Wd, bd,
                                (float*)d_out, out_size);
}